// round 10
// baseline (speedup 1.0000x reference)
#include <cuda_runtime.h>
#include <cuda_fp16.h>
#include <math.h>
#include <stdint.h>

#define BATCH 16
#define CH 512
#define HW 4096
#define KTOT 4608           // 512 c * 9 taps
#define KITERS 72           // 4608 / 64
#define GTHR 256
#define STAGES 3
#define A_BYTES 16384       // 128 x 64 fp16
#define B_BYTES 16384       // 128 x 64 fp16
#define STAGE_BYTES (A_BYTES + B_BYTES)
#define SMEM_GEMM (STAGES * STAGE_BYTES)   // 96KB per CTA, 2 CTAs/SM

// ---------------- scratch ----------------
__device__ float g_s[BATCH * CH];
__device__ float g_s2[BATCH * CH];
__device__ float g_dcoef[BATCH * CH];
__device__ float g_wsq[CH * CH];
__device__ __half g_A[BATCH * CH * KTOT];   // modulated weights [b][o][ck]
__device__ __half g_B[HW * KTOT];           // im2col patches  [p][ck]

__device__ __forceinline__ uint32_t s2u(const void* p) {
    return (uint32_t)__cvta_generic_to_shared(p);
}
__device__ __forceinline__ uint32_t swzoff(uint32_t row, uint32_t chunk) {
    return row * 128u + ((chunk ^ (row & 7u)) << 4);
}
__device__ __forceinline__ void cpa16(uint32_t s, const void* g) {
    asm volatile("cp.async.cg.shared.global [%0], [%1], 16;" :: "r"(s), "l"(g));
}
__device__ __forceinline__ void ldm4(uint32_t addr, uint32_t& r0, uint32_t& r1,
                                     uint32_t& r2, uint32_t& r3) {
    asm volatile("ldmatrix.sync.aligned.m8n8.x4.shared.b16 {%0,%1,%2,%3}, [%4];"
                 : "=r"(r0), "=r"(r1), "=r"(r2), "=r"(r3) : "r"(addr));
}
__device__ __forceinline__ void hmma(float* d, const uint32_t* a, const uint32_t* bf) {
    asm volatile(
        "mma.sync.aligned.m16n8k16.row.col.f32.f16.f16.f32 "
        "{%0,%1,%2,%3}, {%4,%5,%6,%7}, {%8,%9}, {%0,%1,%2,%3};"
        : "+f"(d[0]), "+f"(d[1]), "+f"(d[2]), "+f"(d[3])
        : "r"(a[0]), "r"(a[1]), "r"(a[2]), "r"(a[3]), "r"(bf[0]), "r"(bf[1]));
}

// ---------------- prep0: styles + wsq ----------------
__global__ void k_prep0(const float* __restrict__ ws, const float* __restrict__ caw,
                        const float* __restrict__ cab, const float* __restrict__ raw,
                        const float* __restrict__ rab, const float* __restrict__ cw) {
    if (blockIdx.x < 1024) {
        int widx = blockIdx.x * 8 + (threadIdx.x >> 5);
        int lane = threadIdx.x & 31;
        int b = widx >> 9, c = widx & 511;
        const float* w0 = ws + b * 1024;
        const float* w1 = w0 + 512;
        const float* ca = caw + c * 512;
        const float* ra = raw + c * 512;
        float a1 = 0.f, a2 = 0.f;
        for (int d = lane; d < 512; d += 32) {
            a1 = fmaf(w0[d], ca[d], a1);
            a2 = fmaf(w1[d], ra[d], a2);
        }
        #pragma unroll
        for (int o = 16; o; o >>= 1) {
            a1 += __shfl_xor_sync(0xffffffffu, a1, o);
            a2 += __shfl_xor_sync(0xffffffffu, a2, o);
        }
        if (lane == 0) {
            g_s[b * 512 + c] = a1 + cab[c];
            g_s2[b * 512 + c] = (a2 + rab[c]) * 0.04419417382415922f;
        }
    } else {
        int idx = (blockIdx.x - 1024) * 256 + threadIdx.x;
        const float* p = cw + (size_t)idx * 9;
        float s = 0.f;
        #pragma unroll
        for (int k = 0; k < 9; k++) s = fmaf(p[k], p[k], s);
        g_wsq[idx] = s;
    }
}

// ---------------- dcoef ----------------
__global__ void k_dcoef() {
    int widx = blockIdx.x * 8 + (threadIdx.x >> 5);
    int lane = threadIdx.x & 31;
    int b = widx >> 9, o = widx & 511;
    const float* wq = g_wsq + o * 512;
    const float* sp = g_s + b * 512;
    float a = 0.f;
    for (int c = lane; c < 512; c += 32) {
        float sv = sp[c];
        a = fmaf(wq[c] * sv, sv, a);
    }
    #pragma unroll
    for (int off = 16; off; off >>= 1) a += __shfl_xor_sync(0xffffffffu, a, off);
    if (!lane) g_dcoef[b * 512 + o] = rsqrtf(a + 1e-8f);
}

// ---------------- prep1: A prep (x8) + B prep (x8) ----------------
__global__ void k_prep1(const float* __restrict__ cw, const float* __restrict__ cst) {
    if (blockIdx.x < 18432) {
        int idx = blockIdx.x * 256 + threadIdx.x;
        int ck8 = (idx % (KTOT / 8)) * 8;
        int rem = idx / (KTOT / 8);
        int o = rem & 511;
        int b = rem >> 9;
        const float* sp = g_s + b * 512;
        const float* wp = cw + (size_t)o * KTOT + ck8;
        float4 f0 = *(const float4*)(wp);
        float4 f1 = *(const float4*)(wp + 4);
        __half h[8];
        #pragma unroll
        for (int j = 0; j < 8; j++) {
            int c = (unsigned)(ck8 + j) / 9u;
            float wv = (j < 4) ? ((const float*)&f0)[j] : ((const float*)&f1)[j - 4];
            h[j] = __float2half_rn(wv * sp[c]);
        }
        *(uint4*)(g_A + (size_t)idx * 8) = *(const uint4*)h;
    } else {
        int idx = (blockIdx.x - 18432) * 256 + threadIdx.x;   // over HW*KTOT/8
        int ck8 = (idx % (KTOT / 8)) * 8;
        int p = idx / (KTOT / 8);
        int py = p >> 6, px = p & 63;
        __half h[8];
        #pragma unroll
        for (int j = 0; j < 8; j++) {
            int ck = ck8 + j;
            int c = (unsigned)ck / 9u;
            int k = ck - c * 9;
            int ky = (unsigned)k / 3u;
            int kx = k - ky * 3;
            int yy = py + ky - 1;
            int xx = px + kx - 1;
            float v = 0.f;
            if ((unsigned)yy < 64u && (unsigned)xx < 64u)
                v = cst[c * 4096 + yy * 64 + xx];
            h[j] = __float2half_rn(v);
        }
        *(uint4*)(g_B + (size_t)idx * 8) = *(const uint4*)h;
    }
}

// ---------------- main GEMM: CTA 128x128, warp 64x32, 2 CTAs/SM, k16 rotation ----------------
__global__ __launch_bounds__(GTHR, 2)
void k_gemm(const float* __restrict__ nzc, const float* __restrict__ nzs,
            const float* __restrict__ cb, float* __restrict__ out) {
    extern __shared__ char smem[];
    const uint32_t sb = s2u(smem);

    const int tid = threadIdx.x;
    const int wid = tid >> 5;
    const int lane = tid & 31;
    const int wm = wid & 1;        // 2 m-bands of 64
    const int wn = wid >> 1;       // 4 n-bands of 32
    const uint32_t rot = wid & 3;  // per-warp k16 phase rotation

    const int b = blockIdx.z;
    const int obase = blockIdx.y * 128;
    const int pbase = blockIdx.x * 128;

    const char* Ag = (const char*)(g_A + (size_t)(b * 512 + obase) * KTOT);
    const char* Bg = (const char*)(g_B + (size_t)pbase * KTOT);

    float acc[4][4][4];
    #pragma unroll
    for (int mi = 0; mi < 4; mi++)
        #pragma unroll
        for (int nj = 0; nj < 4; nj++)
            #pragma unroll
            for (int q = 0; q < 4; q++) acc[mi][nj][q] = 0.f;

    #define FILL(KI, STG) do {                                                    \
        size_t kb = (size_t)(KI) * 128;                                           \
        uint32_t sA = sb + (STG) * STAGE_BYTES;                                   \
        uint32_t sBs = sA + A_BYTES;                                              \
        _Pragma("unroll")                                                         \
        for (int j = 0; j < 4; j++) {                                             \
            int idx = tid + j * GTHR;                                             \
            uint32_t row = idx >> 3, cv = idx & 7;                                \
            cpa16(sA + swzoff(row, cv),                                           \
                  Ag + (size_t)row * (KTOT * 2) + kb + cv * 16);                  \
        }                                                                         \
        _Pragma("unroll")                                                         \
        for (int j = 0; j < 4; j++) {                                             \
            int idx = tid + j * GTHR;                                             \
            uint32_t row = idx >> 3, cv = idx & 7;                                \
            cpa16(sBs + swzoff(row, cv),                                          \
                  Bg + (size_t)row * (KTOT * 2) + kb + cv * 16);                  \
        }                                                                         \
        asm volatile("cp.async.commit_group;" ::: "memory");                      \
    } while (0)

    FILL(0, 0);
    FILL(1, 1);

    int stg = 0;
    for (int i = 0; i < KITERS; i++) {
        asm volatile("cp.async.wait_group 1;" ::: "memory");
        __syncthreads();

        if (i + 2 < KITERS) {
            int ns = stg + 2;
            if (ns >= STAGES) ns -= STAGES;
            FILL(i + 2, ns);
        } else {
            asm volatile("cp.async.commit_group;" ::: "memory");
        }

        const uint32_t sA = sb + stg * STAGE_BYTES;
        const uint32_t sBs = sA + A_BYTES;

        // B frags double-buffered; k16 order rotated per warp.
        uint32_t bbuf[2][2][4];
        {   // preload B for first rotated k16
            const uint32_t kc = rot * 2;
            #pragma unroll
            for (int njp = 0; njp < 2; njp++) {
                uint32_t row = wn * 32 + njp * 16 + ((lane >> 4) << 3) + (lane & 7);
                uint32_t chunk = kc + ((lane >> 3) & 1);
                ldm4(sBs + swzoff(row, chunk),
                     bbuf[0][njp][0], bbuf[0][njp][1], bbuf[0][njp][2], bbuf[0][njp][3]);
            }
        }
        #pragma unroll
        for (int j = 0; j < 4; j++) {
            const uint32_t kk = (rot + j) & 3;
            const uint32_t kc = kk * 2;
            const int cur = j & 1, nxt = cur ^ 1;

            uint32_t a[4][4];
            #pragma unroll
            for (int mi = 0; mi < 4; mi++) {
                uint32_t row = wm * 64 + mi * 16 + (lane & 15);
                uint32_t chunk = kc + (lane >> 4);
                ldm4(sA + swzoff(row, chunk), a[mi][0], a[mi][1], a[mi][2], a[mi][3]);
            }
            if (j < 3) {   // prefetch next k16's B under this k16's mma
                const uint32_t knc = ((rot + j + 1) & 3) * 2;
                #pragma unroll
                for (int njp = 0; njp < 2; njp++) {
                    uint32_t row = wn * 32 + njp * 16 + ((lane >> 4) << 3) + (lane & 7);
                    uint32_t chunk = knc + ((lane >> 3) & 1);
                    ldm4(sBs + swzoff(row, chunk),
                         bbuf[nxt][njp][0], bbuf[nxt][njp][1], bbuf[nxt][njp][2], bbuf[nxt][njp][3]);
                }
            }
            #pragma unroll
            for (int mi = 0; mi < 4; mi++)
                #pragma unroll
                for (int nj = 0; nj < 4; nj++)
                    hmma(acc[mi][nj], a[mi], &bbuf[cur][nj >> 1][(nj & 1) * 2]);
        }
        stg = (stg + 1 == STAGES) ? 0 : stg + 1;
    }

    // ---------------- fused epilogue ----------------
    const float nst = nzs[0];
    const float gain = 1.4142135623730951f;
    const int r0 = lane >> 2;
    const int cpair = (lane & 3) * 2;

    float nzv[4][2];
    #pragma unroll
    for (int nj = 0; nj < 4; nj++) {
        int p = pbase + wn * 32 + nj * 8 + cpair;
        nzv[nj][0] = nzc[p] * nst;
        nzv[nj][1] = nzc[p + 1] * nst;
    }

    #pragma unroll
    for (int mi = 0; mi < 4; mi++) {
        #pragma unroll
        for (int h = 0; h < 2; h++) {
            int o = obase + wm * 64 + mi * 16 + h * 8 + r0;
            float dc = g_dcoef[b * 512 + o];
            float bias = cb[o];
            float* orow = out + (size_t)(b * 512 + o) * HW;
            #pragma unroll
            for (int nj = 0; nj < 4; nj++) {
                int p = pbase + wn * 32 + nj * 8 + cpair;
                float z0 = fmaf(acc[mi][nj][2 * h],     dc, nzv[nj][0] + bias);
                float z1 = fmaf(acc[mi][nj][2 * h + 1], dc, nzv[nj][1] + bias);
                float2 v;
                v.x = (z0 > 0.f ? z0 : 0.2f * z0) * gain;
                v.y = (z1 > 0.f ? z1 : 0.2f * z1) * gain;
                *(float2*)(orow + p) = v;
            }
        }
    }
}

// ---------------- ToRGB (float4 vectorized) ----------------
__global__ void k_rgb(const float* __restrict__ x, const float* __restrict__ rgbw,
                      const float* __restrict__ rgbb, float* __restrict__ img) {
    __shared__ float rw[3][512];
    int b = blockIdx.y;
    int px4 = blockIdx.x * 256 + threadIdx.x;   // float4 index
    for (int i = threadIdx.x; i < 1536; i += 256) {
        int ch = i >> 9, o = i & 511;
        rw[ch][o] = rgbw[ch * 512 + o] * g_s2[b * 512 + o];
    }
    __syncthreads();
    const float4* xp = (const float4*)(x + (size_t)b * CH * HW) + px4;
    float4 a0 = {0.f, 0.f, 0.f, 0.f}, a1 = a0, a2 = a0;
    #pragma unroll 4
    for (int o = 0; o < 512; o++) {
        float4 xv = xp[o * (HW / 4)];
        float w0 = rw[0][o], w1 = rw[1][o], w2 = rw[2][o];
        a0.x = fmaf(w0, xv.x, a0.x); a0.y = fmaf(w0, xv.y, a0.y);
        a0.z = fmaf(w0, xv.z, a0.z); a0.w = fmaf(w0, xv.w, a0.w);
        a1.x = fmaf(w1, xv.x, a1.x); a1.y = fmaf(w1, xv.y, a1.y);
        a1.z = fmaf(w1, xv.z, a1.z); a1.w = fmaf(w1, xv.w, a1.w);
        a2.x = fmaf(w2, xv.x, a2.x); a2.y = fmaf(w2, xv.y, a2.y);
        a2.z = fmaf(w2, xv.z, a2.z); a2.w = fmaf(w2, xv.w, a2.w);
    }
    float b0 = rgbb[0], b1 = rgbb[1], b2 = rgbb[2];
    a0.x += b0; a0.y += b0; a0.z += b0; a0.w += b0;
    a1.x += b1; a1.y += b1; a1.z += b1; a1.w += b1;
    a2.x += b2; a2.y += b2; a2.z += b2; a2.w += b2;
    float4* ob = (float4*)(img + (size_t)b * 3 * HW) + px4;
    ob[0] = a0;
    ob[HW / 4] = a1;
    ob[2 * (HW / 4)] = a2;
}

extern "C" void kernel_launch(void* const* d_in, const int* in_sizes, int n_in,
                              void* d_out, int out_size) {
    const float* ws   = (const float*)d_in[0];
    const float* cst  = (const float*)d_in[1];
    const float* cw   = (const float*)d_in[2];
    const float* cb   = (const float*)d_in[3];
    const float* caw  = (const float*)d_in[4];
    const float* cab  = (const float*)d_in[5];
    const float* nzc  = (const float*)d_in[6];
    const float* nzs  = (const float*)d_in[7];
    const float* rgbw = (const float*)d_in[8];
    const float* rgbb = (const float*)d_in[9];
    const float* raw  = (const float*)d_in[10];
    const float* rab  = (const float*)d_in[11];
    float* out = (float*)d_out;

    cudaFuncSetAttribute(k_gemm, cudaFuncAttributeMaxDynamicSharedMemorySize, SMEM_GEMM);

    k_prep0<<<2048, 256>>>(ws, caw, cab, raw, rab, cw);          // launch 0
    k_dcoef<<<1024, 256>>>();                                    // launch 1
    k_prep1<<<18432 + 9216, 256>>>(cw, cst);                     // launch 2
    dim3 g(HW / 128, CH / 128, BATCH);                           // (32, 4, 16)
    k_gemm<<<g, GTHR, SMEM_GEMM>>>(nzc, nzs, cb, out);           // launch 3 (profiled)
    k_rgb<<<dim3(4, 16), 256>>>(out, rgbw, rgbb, out + (size_t)BATCH * CH * HW);
}

// round 12
// speedup vs baseline: 1.1033x; 1.1033x over previous
#include <cuda_runtime.h>
#include <cuda_fp16.h>
#include <math.h>
#include <stdint.h>

#define BATCH 16
#define CH 512
#define HW 4096
#define KTOT 4608           // 512 c * 9 taps
#define KITERS 72           // 4608 / 64
#define GTHR 256
#define STAGES 3
#define A_BYTES 16384       // 128 x 64 fp16
#define B_BYTES 16384       // 128 x 64 fp16
#define STAGE_BYTES (A_BYTES + B_BYTES)
#define SMEM_GEMM (STAGES * STAGE_BYTES)   // 96KB per CTA, 2 CTAs/SM

// ---------------- scratch ----------------
__device__ float g_s[BATCH * CH];
__device__ float g_s2[BATCH * CH];
__device__ float g_dcoef[BATCH * CH];
__device__ float g_wsq[CH * CH];
__device__ float g_rwp[BATCH * 3 * CH];     // rgb_w[ch,o] * s2[b,o]
__device__ __half g_A[BATCH * CH * KTOT];   // modulated weights [b][o][ck]
__device__ __half g_B[HW * KTOT];           // im2col patches  [p][ck]

__device__ __forceinline__ uint32_t s2u(const void* p) {
    return (uint32_t)__cvta_generic_to_shared(p);
}
__device__ __forceinline__ uint32_t swzoff(uint32_t row, uint32_t chunk) {
    return row * 128u + ((chunk ^ (row & 7u)) << 4);
}
__device__ __forceinline__ void cpa16(uint32_t s, const void* g) {
    asm volatile("cp.async.cg.shared.global [%0], [%1], 16;" :: "r"(s), "l"(g));
}
__device__ __forceinline__ void ldm4(uint32_t addr, uint32_t& r0, uint32_t& r1,
                                     uint32_t& r2, uint32_t& r3) {
    asm volatile("ldmatrix.sync.aligned.m8n8.x4.shared.b16 {%0,%1,%2,%3}, [%4];"
                 : "=r"(r0), "=r"(r1), "=r"(r2), "=r"(r3) : "r"(addr));
}
__device__ __forceinline__ void hmma(float* d, const uint32_t* a, const uint32_t* bf) {
    asm volatile(
        "mma.sync.aligned.m16n8k16.row.col.f32.f16.f16.f32 "
        "{%0,%1,%2,%3}, {%4,%5,%6,%7}, {%8,%9}, {%0,%1,%2,%3};"
        : "+f"(d[0]), "+f"(d[1]), "+f"(d[2]), "+f"(d[3])
        : "r"(a[0]), "r"(a[1]), "r"(a[2]), "r"(a[3]), "r"(bf[0]), "r"(bf[1]));
}

// ---------------- prep0: styles + wsq + img bias init ----------------
__global__ void k_prep0(const float* __restrict__ ws, const float* __restrict__ caw,
                        const float* __restrict__ cab, const float* __restrict__ raw,
                        const float* __restrict__ rab, const float* __restrict__ cw,
                        const float* __restrict__ rgbb, float* __restrict__ img) {
    if (blockIdx.x < 1024) {
        int widx = blockIdx.x * 8 + (threadIdx.x >> 5);
        int lane = threadIdx.x & 31;
        int b = widx >> 9, c = widx & 511;
        const float* w0 = ws + b * 1024;
        const float* w1 = w0 + 512;
        const float* ca = caw + c * 512;
        const float* ra = raw + c * 512;
        float a1 = 0.f, a2 = 0.f;
        for (int d = lane; d < 512; d += 32) {
            a1 = fmaf(w0[d], ca[d], a1);
            a2 = fmaf(w1[d], ra[d], a2);
        }
        #pragma unroll
        for (int o = 16; o; o >>= 1) {
            a1 += __shfl_xor_sync(0xffffffffu, a1, o);
            a2 += __shfl_xor_sync(0xffffffffu, a2, o);
        }
        if (lane == 0) {
            g_s[b * 512 + c] = a1 + cab[c];
            g_s2[b * 512 + c] = (a2 + rab[c]) * 0.04419417382415922f;
        }
    } else if (blockIdx.x < 2048) {
        int idx = (blockIdx.x - 1024) * 256 + threadIdx.x;
        const float* p = cw + (size_t)idx * 9;
        float s = 0.f;
        #pragma unroll
        for (int k = 0; k < 9; k++) s = fmaf(p[k], p[k], s);
        g_wsq[idx] = s;
    } else {
        // img bias init: 16*3*4096 = 196608 elems over 768 blocks
        int idx = (blockIdx.x - 2048) * 256 + threadIdx.x;
        int ch = (idx >> 12) % 3;
        img[idx] = rgbb[ch];
    }
}

// ---------------- dcoef + rwp ----------------
__global__ void k_dcoef(const float* __restrict__ rgbw) {
    if (blockIdx.x < 1024) {
        int widx = blockIdx.x * 8 + (threadIdx.x >> 5);
        int lane = threadIdx.x & 31;
        int b = widx >> 9, o = widx & 511;
        const float* wq = g_wsq + o * 512;
        const float* sp = g_s + b * 512;
        float a = 0.f;
        for (int c = lane; c < 512; c += 32) {
            float sv = sp[c];
            a = fmaf(wq[c] * sv, sv, a);
        }
        #pragma unroll
        for (int off = 16; off; off >>= 1) a += __shfl_xor_sync(0xffffffffu, a, off);
        if (!lane) g_dcoef[b * 512 + o] = rsqrtf(a + 1e-8f);
    } else {
        // rwp[b][ch][o] = rgbw[ch*512+o] * g_s2[b*512+o]; 24576 elems over 96 blocks
        int idx = (blockIdx.x - 1024) * 256 + threadIdx.x;
        int b = idx / 1536;
        int r = idx - b * 1536;
        int ch = r >> 9, o = r & 511;
        g_rwp[idx] = rgbw[ch * 512 + o] * g_s2[b * 512 + o];
    }
}

// ---------------- prep1: A prep (x8) + B prep (x8) ----------------
__global__ void k_prep1(const float* __restrict__ cw, const float* __restrict__ cst) {
    if (blockIdx.x < 18432) {
        int idx = blockIdx.x * 256 + threadIdx.x;
        int ck8 = (idx % (KTOT / 8)) * 8;
        int rem = idx / (KTOT / 8);
        int o = rem & 511;
        int b = rem >> 9;
        const float* sp = g_s + b * 512;
        const float* wp = cw + (size_t)o * KTOT + ck8;
        float4 f0 = *(const float4*)(wp);
        float4 f1 = *(const float4*)(wp + 4);
        __half h[8];
        #pragma unroll
        for (int j = 0; j < 8; j++) {
            int c = (unsigned)(ck8 + j) / 9u;
            float wv = (j < 4) ? ((const float*)&f0)[j] : ((const float*)&f1)[j - 4];
            h[j] = __float2half_rn(wv * sp[c]);
        }
        *(uint4*)(g_A + (size_t)idx * 8) = *(const uint4*)h;
    } else {
        int idx = (blockIdx.x - 18432) * 256 + threadIdx.x;   // over HW*KTOT/8
        int ck8 = (idx % (KTOT / 8)) * 8;
        int p = idx / (KTOT / 8);
        int py = p >> 6, px = p & 63;
        __half h[8];
        #pragma unroll
        for (int j = 0; j < 8; j++) {
            int ck = ck8 + j;
            int c = (unsigned)ck / 9u;
            int k = ck - c * 9;
            int ky = (unsigned)k / 3u;
            int kx = k - ky * 3;
            int yy = py + ky - 1;
            int xx = px + kx - 1;
            float v = 0.f;
            if ((unsigned)yy < 64u && (unsigned)xx < 64u)
                v = cst[c * 4096 + yy * 64 + xx];
            h[j] = __float2half_rn(v);
        }
        *(uint4*)(g_B + (size_t)idx * 8) = *(const uint4*)h;
    }
}

// ---------------- main GEMM: CTA 128x128, warp 64x32, 2 CTAs/SM, fused RGB ----------------
__global__ __launch_bounds__(GTHR, 2)
void k_gemm(const float* __restrict__ nzc, const float* __restrict__ nzs,
            const float* __restrict__ cb, float* __restrict__ out,
            float* __restrict__ img) {
    extern __shared__ char smem[];
    const uint32_t sb = s2u(smem);

    const int tid = threadIdx.x;
    const int wid = tid >> 5;
    const int lane = tid & 31;
    const int wm = wid & 1;        // 2 m-bands of 64
    const int wn = wid >> 1;       // 4 n-bands of 32

    const int b = blockIdx.z;
    const int obase = blockIdx.y * 128;
    const int pbase = blockIdx.x * 128;

    const char* Ag = (const char*)(g_A + (size_t)(b * 512 + obase) * KTOT);
    const char* Bg = (const char*)(g_B + (size_t)pbase * KTOT);

    float acc[4][4][4];
    #pragma unroll
    for (int mi = 0; mi < 4; mi++)
        #pragma unroll
        for (int nj = 0; nj < 4; nj++)
            #pragma unroll
            for (int q = 0; q < 4; q++) acc[mi][nj][q] = 0.f;

    #define FILL(KI, STG) do {                                                    \
        size_t kb = (size_t)(KI) * 128;                                           \
        uint32_t sA = sb + (STG) * STAGE_BYTES;                                   \
        uint32_t sBs = sA + A_BYTES;                                              \
        _Pragma("unroll")                                                         \
        for (int j = 0; j < 4; j++) {                                             \
            int idx = tid + j * GTHR;                                             \
            uint32_t row = idx >> 3, cv = idx & 7;                                \
            cpa16(sA + swzoff(row, cv),                                           \
                  Ag + (size_t)row * (KTOT * 2) + kb + cv * 16);                  \
        }                                                                         \
        _Pragma("unroll")                                                         \
        for (int j = 0; j < 4; j++) {                                             \
            int idx = tid + j * GTHR;                                             \
            uint32_t row = idx >> 3, cv = idx & 7;                                \
            cpa16(sBs + swzoff(row, cv),                                          \
                  Bg + (size_t)row * (KTOT * 2) + kb + cv * 16);                  \
        }                                                                         \
        asm volatile("cp.async.commit_group;" ::: "memory");                      \
    } while (0)

    FILL(0, 0);
    FILL(1, 1);

    int stg = 0;
    for (int i = 0; i < KITERS; i++) {
        asm volatile("cp.async.wait_group 1;" ::: "memory");
        __syncthreads();

        if (i + 2 < KITERS) {
            int ns = stg + 2;
            if (ns >= STAGES) ns -= STAGES;
            FILL(i + 2, ns);
        } else {
            asm volatile("cp.async.commit_group;" ::: "memory");
        }

        const uint32_t sA = sb + stg * STAGE_BYTES;
        const uint32_t sBs = sA + A_BYTES;

        #pragma unroll
        for (int k16 = 0; k16 < 4; k16++) {
            const uint32_t kc = k16 * 2;
            uint32_t a[4][4], br[2][4];
            #pragma unroll
            for (int mi = 0; mi < 4; mi++) {
                uint32_t row = wm * 64 + mi * 16 + (lane & 15);
                uint32_t chunk = kc + (lane >> 4);
                ldm4(sA + swzoff(row, chunk), a[mi][0], a[mi][1], a[mi][2], a[mi][3]);
            }
            #pragma unroll
            for (int njp = 0; njp < 2; njp++) {
                uint32_t row = wn * 32 + njp * 16 + ((lane >> 4) << 3) + (lane & 7);
                uint32_t chunk = kc + ((lane >> 3) & 1);
                ldm4(sBs + swzoff(row, chunk), br[njp][0], br[njp][1], br[njp][2], br[njp][3]);
            }
            #pragma unroll
            for (int mi = 0; mi < 4; mi++)
                #pragma unroll
                for (int nj = 0; nj < 4; nj++)
                    hmma(acc[mi][nj], a[mi], &br[nj >> 1][(nj & 1) * 2]);
        }
        stg = (stg + 1 == STAGES) ? 0 : stg + 1;
    }

    // ---------------- fused epilogue: x (demod/noise/bias/lrelu) + rgb partials ----------------
    const float nst = nzs[0];
    const float gain = 1.4142135623730951f;
    const int r0 = lane >> 2;
    const int cpair = (lane & 3) * 2;

    float nzv[4][2];
    #pragma unroll
    for (int nj = 0; nj < 4; nj++) {
        int p = pbase + wn * 32 + nj * 8 + cpair;
        nzv[nj][0] = nzc[p] * nst;
        nzv[nj][1] = nzc[p + 1] * nst;
    }

    float pr[3][8];   // [ch][nj*2+half] rgb partial sums over this thread's 8 o's
    #pragma unroll
    for (int ch = 0; ch < 3; ch++)
        #pragma unroll
        for (int j = 0; j < 8; j++) pr[ch][j] = 0.f;

    const float* rwp = g_rwp + b * 1536;

    #pragma unroll
    for (int mi = 0; mi < 4; mi++) {
        #pragma unroll
        for (int h = 0; h < 2; h++) {
            int o = obase + wm * 64 + mi * 16 + h * 8 + r0;
            float dc = g_dcoef[b * 512 + o];
            float bias = cb[o];
            float rw0 = rwp[o], rw1 = rwp[512 + o], rw2 = rwp[1024 + o];
            float* orow = out + (size_t)(b * 512 + o) * HW;
            #pragma unroll
            for (int nj = 0; nj < 4; nj++) {
                int p = pbase + wn * 32 + nj * 8 + cpair;
                float z0 = fmaf(acc[mi][nj][2 * h],     dc, nzv[nj][0] + bias);
                float z1 = fmaf(acc[mi][nj][2 * h + 1], dc, nzv[nj][1] + bias);
                float2 v;
                v.x = (z0 > 0.f ? z0 : 0.2f * z0) * gain;
                v.y = (z1 > 0.f ? z1 : 0.2f * z1) * gain;
                *(float2*)(orow + p) = v;
                pr[0][nj * 2]     = fmaf(rw0, v.x, pr[0][nj * 2]);
                pr[0][nj * 2 + 1] = fmaf(rw0, v.y, pr[0][nj * 2 + 1]);
                pr[1][nj * 2]     = fmaf(rw1, v.x, pr[1][nj * 2]);
                pr[1][nj * 2 + 1] = fmaf(rw1, v.y, pr[1][nj * 2 + 1]);
                pr[2][nj * 2]     = fmaf(rw2, v.x, pr[2][nj * 2]);
                pr[2][nj * 2 + 1] = fmaf(rw2, v.y, pr[2][nj * 2 + 1]);
            }
        }
    }

    // reduce rgb partials: smem tile [3][128] then one global red.add per slot
    float* img_s = (float*)smem;
    __syncthreads();                 // mainloop smem reads done; safe to reuse
    for (int i = tid; i < 384; i += GTHR) img_s[i] = 0.f;
    __syncthreads();
    #pragma unroll
    for (int ch = 0; ch < 3; ch++)
        #pragma unroll
        for (int j = 0; j < 8; j++) {
            int px = wn * 32 + (j >> 1) * 8 + cpair + (j & 1);
            atomicAdd(&img_s[ch * 128 + px], pr[ch][j]);
        }
    __syncthreads();
    for (int i = tid; i < 384; i += GTHR) {
        int ch = i >> 7, px = i & 127;
        atomicAdd(&img[((size_t)b * 3 + ch) * HW + pbase + px], img_s[i]);
    }
}

extern "C" void kernel_launch(void* const* d_in, const int* in_sizes, int n_in,
                              void* d_out, int out_size) {
    const float* ws   = (const float*)d_in[0];
    const float* cst  = (const float*)d_in[1];
    const float* cw   = (const float*)d_in[2];
    const float* cb   = (const float*)d_in[3];
    const float* caw  = (const float*)d_in[4];
    const float* cab  = (const float*)d_in[5];
    const float* nzc  = (const float*)d_in[6];
    const float* nzs  = (const float*)d_in[7];
    const float* rgbw = (const float*)d_in[8];
    const float* rgbb = (const float*)d_in[9];
    const float* raw  = (const float*)d_in[10];
    const float* rab  = (const float*)d_in[11];
    float* out = (float*)d_out;
    float* img = out + (size_t)BATCH * CH * HW;

    cudaFuncSetAttribute(k_gemm, cudaFuncAttributeMaxDynamicSharedMemorySize, SMEM_GEMM);

    k_prep0<<<2048 + 768, 256>>>(ws, caw, cab, raw, rab, cw, rgbb, img);  // launch 0
    k_dcoef<<<1024 + 96, 256>>>(rgbw);                                    // launch 1
    k_prep1<<<18432 + 9216, 256>>>(cw, cst);                              // launch 2
    dim3 g(HW / 128, CH / 128, BATCH);                                    // (32, 4, 16)
    k_gemm<<<g, GTHR, SMEM_GEMM>>>(nzc, nzs, cb, out, img);               // launch 3 (profiled)
}

// round 13
// speedup vs baseline: 1.1853x; 1.0743x over previous
#include <cuda_runtime.h>
#include <cuda_fp16.h>
#include <math.h>
#include <stdint.h>

#define BATCH 16
#define CH 512
#define HW 4096
#define KTOT 4608           // 512 c * 9 taps
#define KITERS 72           // 4608 / 64
#define GTHR 256
#define STAGES 3
#define A_BYTES 16384       // 128 x 64 fp16
#define B_BYTES 16384       // 128 x 64 fp16
#define STAGE_BYTES (A_BYTES + B_BYTES)
#define SMEM_GEMM (STAGES * STAGE_BYTES)   // 96KB per CTA, 2 CTAs/SM

// ---------------- scratch ----------------
__device__ float g_s[BATCH * CH];
__device__ float g_s2[BATCH * CH];
__device__ float g_dcoef[BATCH * CH];
__device__ float g_wsq[CH * CH];
__device__ float g_rwp[BATCH * 3 * CH];     // rgb_w[ch,o] * s2[b,o]
__device__ __half g_A[BATCH * CH * KTOT];   // modulated weights [b][o][ck]
__device__ __half g_B[HW * KTOT];           // im2col patches  [p][ck]

__device__ __forceinline__ uint32_t s2u(const void* p) {
    return (uint32_t)__cvta_generic_to_shared(p);
}
__device__ __forceinline__ uint32_t swzoff(uint32_t row, uint32_t chunk) {
    return row * 128u + ((chunk ^ (row & 7u)) << 4);
}
__device__ __forceinline__ void cpa16(uint32_t s, const void* g) {
    asm volatile("cp.async.cg.shared.global [%0], [%1], 16;" :: "r"(s), "l"(g));
}
__device__ __forceinline__ void ldm4(uint32_t addr, uint32_t& r0, uint32_t& r1,
                                     uint32_t& r2, uint32_t& r3) {
    asm volatile("ldmatrix.sync.aligned.m8n8.x4.shared.b16 {%0,%1,%2,%3}, [%4];"
                 : "=r"(r0), "=r"(r1), "=r"(r2), "=r"(r3) : "r"(addr));
}
__device__ __forceinline__ void hmma(float* d, const uint32_t* a, const uint32_t* bf) {
    asm volatile(
        "mma.sync.aligned.m16n8k16.row.col.f32.f16.f16.f32 "
        "{%0,%1,%2,%3}, {%4,%5,%6,%7}, {%8,%9}, {%0,%1,%2,%3};"
        : "+f"(d[0]), "+f"(d[1]), "+f"(d[2]), "+f"(d[3])
        : "r"(a[0]), "r"(a[1]), "r"(a[2]), "r"(a[3]), "r"(bf[0]), "r"(bf[1]));
}

// ---------------- prep0: styles + wsq + img bias init ----------------
__global__ void k_prep0(const float* __restrict__ ws, const float* __restrict__ caw,
                        const float* __restrict__ cab, const float* __restrict__ raw,
                        const float* __restrict__ rab, const float* __restrict__ cw,
                        const float* __restrict__ rgbb, float* __restrict__ img) {
    if (blockIdx.x < 1024) {
        int widx = blockIdx.x * 8 + (threadIdx.x >> 5);
        int lane = threadIdx.x & 31;
        int b = widx >> 9, c = widx & 511;
        const float* w0 = ws + b * 1024;
        const float* w1 = w0 + 512;
        const float* ca = caw + c * 512;
        const float* ra = raw + c * 512;
        float a1 = 0.f, a2 = 0.f;
        for (int d = lane; d < 512; d += 32) {
            a1 = fmaf(w0[d], ca[d], a1);
            a2 = fmaf(w1[d], ra[d], a2);
        }
        #pragma unroll
        for (int o = 16; o; o >>= 1) {
            a1 += __shfl_xor_sync(0xffffffffu, a1, o);
            a2 += __shfl_xor_sync(0xffffffffu, a2, o);
        }
        if (lane == 0) {
            g_s[b * 512 + c] = a1 + cab[c];
            g_s2[b * 512 + c] = (a2 + rab[c]) * 0.04419417382415922f;
        }
    } else if (blockIdx.x < 2048) {
        int idx = (blockIdx.x - 1024) * 256 + threadIdx.x;
        const float* p = cw + (size_t)idx * 9;
        float s = 0.f;
        #pragma unroll
        for (int k = 0; k < 9; k++) s = fmaf(p[k], p[k], s);
        g_wsq[idx] = s;
    } else {
        // img bias init: 16*3*4096 = 196608 elems over 768 blocks
        int idx = (blockIdx.x - 2048) * 256 + threadIdx.x;
        int ch = (idx >> 12) % 3;
        img[idx] = rgbb[ch];
    }
}

// ---------------- dcoef + rwp ----------------
__global__ void k_dcoef(const float* __restrict__ rgbw) {
    if (blockIdx.x < 1024) {
        int widx = blockIdx.x * 8 + (threadIdx.x >> 5);
        int lane = threadIdx.x & 31;
        int b = widx >> 9, o = widx & 511;
        const float* wq = g_wsq + o * 512;
        const float* sp = g_s + b * 512;
        float a = 0.f;
        for (int c = lane; c < 512; c += 32) {
            float sv = sp[c];
            a = fmaf(wq[c] * sv, sv, a);
        }
        #pragma unroll
        for (int off = 16; off; off >>= 1) a += __shfl_xor_sync(0xffffffffu, a, off);
        if (!lane) g_dcoef[b * 512 + o] = rsqrtf(a + 1e-8f);
    } else {
        // rwp[b][ch][o] = rgbw[ch*512+o] * g_s2[b*512+o]; 24576 elems over 96 blocks
        int idx = (blockIdx.x - 1024) * 256 + threadIdx.x;
        int b = idx / 1536;
        int r = idx - b * 1536;
        int ch = r >> 9, o = r & 511;
        g_rwp[idx] = rgbw[ch * 512 + o] * g_s2[b * 512 + o];
    }
}

// ---------------- prep1: A prep (x8) + B prep (x8) ----------------
__global__ void k_prep1(const float* __restrict__ cw, const float* __restrict__ cst) {
    if (blockIdx.x < 18432) {
        int idx = blockIdx.x * 256 + threadIdx.x;
        int ck8 = (idx % (KTOT / 8)) * 8;
        int rem = idx / (KTOT / 8);
        int o = rem & 511;
        int b = rem >> 9;
        const float* sp = g_s + b * 512;
        const float* wp = cw + (size_t)o * KTOT + ck8;
        float4 f0 = *(const float4*)(wp);
        float4 f1 = *(const float4*)(wp + 4);
        __half h[8];
        #pragma unroll
        for (int j = 0; j < 8; j++) {
            int c = (unsigned)(ck8 + j) / 9u;
            float wv = (j < 4) ? ((const float*)&f0)[j] : ((const float*)&f1)[j - 4];
            h[j] = __float2half_rn(wv * sp[c]);
        }
        *(uint4*)(g_A + (size_t)idx * 8) = *(const uint4*)h;
    } else {
        int idx = (blockIdx.x - 18432) * 256 + threadIdx.x;   // over HW*KTOT/8
        int ck8 = (idx % (KTOT / 8)) * 8;
        int p = idx / (KTOT / 8);
        int py = p >> 6, px = p & 63;
        __half h[8];
        #pragma unroll
        for (int j = 0; j < 8; j++) {
            int ck = ck8 + j;
            int c = (unsigned)ck / 9u;
            int k = ck - c * 9;
            int ky = (unsigned)k / 3u;
            int kx = k - ky * 3;
            int yy = py + ky - 1;
            int xx = px + kx - 1;
            float v = 0.f;
            if ((unsigned)yy < 64u && (unsigned)xx < 64u)
                v = cst[c * 4096 + yy * 64 + xx];
            h[j] = __float2half_rn(v);
        }
        *(uint4*)(g_B + (size_t)idx * 8) = *(const uint4*)h;
    }
}

// ---------------- main GEMM: CTA 128x128, warp 64x32, 2 CTAs/SM, fused RGB ----------------
__global__ __launch_bounds__(GTHR, 2)
void k_gemm(const float* __restrict__ nzc, const float* __restrict__ nzs,
            const float* __restrict__ cb, float* __restrict__ out,
            float* __restrict__ img) {
    extern __shared__ char smem[];
    const uint32_t sb = s2u(smem);

    const int tid = threadIdx.x;
    const int wid = tid >> 5;
    const int lane = tid & 31;
    const int wm = wid & 1;        // 2 m-bands of 64
    const int wn = wid >> 1;       // 4 n-bands of 32

    const int b = blockIdx.z;
    const int obase = blockIdx.y * 128;
    const int pbase = blockIdx.x * 128;

    const char* Ag = (const char*)(g_A + (size_t)(b * 512 + obase) * KTOT);
    const char* Bg = (const char*)(g_B + (size_t)pbase * KTOT);

    float acc[4][4][4];
    #pragma unroll
    for (int mi = 0; mi < 4; mi++)
        #pragma unroll
        for (int nj = 0; nj < 4; nj++)
            #pragma unroll
            for (int q = 0; q < 4; q++) acc[mi][nj][q] = 0.f;

    #define FILL(KI, STG) do {                                                    \
        size_t kb = (size_t)(KI) * 128;                                           \
        uint32_t sA = sb + (STG) * STAGE_BYTES;                                   \
        uint32_t sBs = sA + A_BYTES;                                              \
        _Pragma("unroll")                                                         \
        for (int j = 0; j < 4; j++) {                                             \
            int idx = tid + j * GTHR;                                             \
            uint32_t row = idx >> 3, cv = idx & 7;                                \
            cpa16(sA + swzoff(row, cv),                                           \
                  Ag + (size_t)row * (KTOT * 2) + kb + cv * 16);                  \
        }                                                                         \
        _Pragma("unroll")                                                         \
        for (int j = 0; j < 4; j++) {                                             \
            int idx = tid + j * GTHR;                                             \
            uint32_t row = idx >> 3, cv = idx & 7;                                \
            cpa16(sBs + swzoff(row, cv),                                          \
                  Bg + (size_t)row * (KTOT * 2) + kb + cv * 16);                  \
        }                                                                         \
        asm volatile("cp.async.commit_group;" ::: "memory");                      \
    } while (0)

    FILL(0, 0);
    FILL(1, 1);

    int stg = 0;
    for (int i = 0; i < KITERS; i++) {
        asm volatile("cp.async.wait_group 1;" ::: "memory");
        __syncthreads();

        if (i + 2 < KITERS) {
            int ns = stg + 2;
            if (ns >= STAGES) ns -= STAGES;
            FILL(i + 2, ns);
        } else {
            asm volatile("cp.async.commit_group;" ::: "memory");
        }

        const uint32_t sA = sb + stg * STAGE_BYTES;
        const uint32_t sBs = sA + A_BYTES;

        #pragma unroll
        for (int k16 = 0; k16 < 4; k16++) {
            const uint32_t kc = k16 * 2;
            uint32_t a[4][4], br[2][4];
            #pragma unroll
            for (int mi = 0; mi < 4; mi++) {
                uint32_t row = wm * 64 + mi * 16 + (lane & 15);
                uint32_t chunk = kc + (lane >> 4);
                ldm4(sA + swzoff(row, chunk), a[mi][0], a[mi][1], a[mi][2], a[mi][3]);
            }
            #pragma unroll
            for (int njp = 0; njp < 2; njp++) {
                uint32_t row = wn * 32 + njp * 16 + ((lane >> 4) << 3) + (lane & 7);
                uint32_t chunk = kc + ((lane >> 3) & 1);
                ldm4(sBs + swzoff(row, chunk), br[njp][0], br[njp][1], br[njp][2], br[njp][3]);
            }
            #pragma unroll
            for (int mi = 0; mi < 4; mi++)
                #pragma unroll
                for (int nj = 0; nj < 4; nj++)
                    hmma(acc[mi][nj], a[mi], &br[nj >> 1][(nj & 1) * 2]);
        }
        stg = (stg + 1 == STAGES) ? 0 : stg + 1;
    }

    // ---------------- fused epilogue: x (demod/noise/bias/lrelu) + rgb partials ----------------
    const float nst = nzs[0];
    const float gain = 1.4142135623730951f;
    const int r0 = lane >> 2;
    const int cpair = (lane & 3) * 2;

    float nzv[4][2];
    #pragma unroll
    for (int nj = 0; nj < 4; nj++) {
        int p = pbase + wn * 32 + nj * 8 + cpair;
        nzv[nj][0] = nzc[p] * nst;
        nzv[nj][1] = nzc[p + 1] * nst;
    }

    float pr[3][8];   // [ch][nj*2+parity] rgb partials over this thread's 8 o's
    #pragma unroll
    for (int ch = 0; ch < 3; ch++)
        #pragma unroll
        for (int j = 0; j < 8; j++) pr[ch][j] = 0.f;

    const float* rwp = g_rwp + b * 1536;

    #pragma unroll
    for (int mi = 0; mi < 4; mi++) {
        #pragma unroll
        for (int h = 0; h < 2; h++) {
            int o = obase + wm * 64 + mi * 16 + h * 8 + r0;
            float dc = g_dcoef[b * 512 + o];
            float bias = cb[o];
            float rw0 = rwp[o], rw1 = rwp[512 + o], rw2 = rwp[1024 + o];
            float* orow = out + (size_t)(b * 512 + o) * HW;
            #pragma unroll
            for (int nj = 0; nj < 4; nj++) {
                int p = pbase + wn * 32 + nj * 8 + cpair;
                float z0 = fmaf(acc[mi][nj][2 * h],     dc, nzv[nj][0] + bias);
                float z1 = fmaf(acc[mi][nj][2 * h + 1], dc, nzv[nj][1] + bias);
                float2 v;
                v.x = (z0 > 0.f ? z0 : 0.2f * z0) * gain;
                v.y = (z1 > 0.f ? z1 : 0.2f * z1) * gain;
                *(float2*)(orow + p) = v;
                pr[0][nj * 2]     = fmaf(rw0, v.x, pr[0][nj * 2]);
                pr[0][nj * 2 + 1] = fmaf(rw0, v.y, pr[0][nj * 2 + 1]);
                pr[1][nj * 2]     = fmaf(rw1, v.x, pr[1][nj * 2]);
                pr[1][nj * 2 + 1] = fmaf(rw1, v.y, pr[1][nj * 2 + 1]);
                pr[2][nj * 2]     = fmaf(rw2, v.x, pr[2][nj * 2]);
                pr[2][nj * 2 + 1] = fmaf(rw2, v.y, pr[2][nj * 2 + 1]);
            }
        }
    }

    // rgb reduction: shuffle over the 8 lanes sharing a pixel (r0), then
    // lanes 0-3 issue one global red.add per (ch, px) — no smem, no ATOMS.
    float* imgb = img + (size_t)b * 3 * HW + pbase;
    #pragma unroll
    for (int ch = 0; ch < 3; ch++) {
        #pragma unroll
        for (int j = 0; j < 8; j++) {
            float v = pr[ch][j];
            v += __shfl_down_sync(0xffffffffu, v, 16);
            v += __shfl_down_sync(0xffffffffu, v, 8);
            v += __shfl_down_sync(0xffffffffu, v, 4);
            if (lane < 4) {
                int px = wn * 32 + (j >> 1) * 8 + lane * 2 + (j & 1);
                atomicAdd(imgb + (size_t)ch * HW + px, v);
            }
        }
    }
}

extern "C" void kernel_launch(void* const* d_in, const int* in_sizes, int n_in,
                              void* d_out, int out_size) {
    const float* ws   = (const float*)d_in[0];
    const float* cst  = (const float*)d_in[1];
    const float* cw   = (const float*)d_in[2];
    const float* cb   = (const float*)d_in[3];
    const float* caw  = (const float*)d_in[4];
    const float* cab  = (const float*)d_in[5];
    const float* nzc  = (const float*)d_in[6];
    const float* nzs  = (const float*)d_in[7];
    const float* rgbw = (const float*)d_in[8];
    const float* rgbb = (const float*)d_in[9];
    const float* raw  = (const float*)d_in[10];
    const float* rab  = (const float*)d_in[11];
    float* out = (float*)d_out;
    float* img = out + (size_t)BATCH * CH * HW;

    cudaFuncSetAttribute(k_gemm, cudaFuncAttributeMaxDynamicSharedMemorySize, SMEM_GEMM);

    k_prep0<<<2048 + 768, 256>>>(ws, caw, cab, raw, rab, cw, rgbb, img);  // launch 0
    k_dcoef<<<1024 + 96, 256>>>(rgbw);                                    // launch 1
    k_prep1<<<18432 + 9216, 256>>>(cw, cst);                              // launch 2
    dim3 g(HW / 128, CH / 128, BATCH);                                    // (32, 4, 16)
    k_gemm<<<g, GTHR, SMEM_GEMM>>>(nzc, nzs, cb, out, img);               // launch 3 (profiled)
}